// round 2
// baseline (speedup 1.0000x reference)
#include <cuda_runtime.h>
#include <cuda_bf16.h>
#include <cstdint>

// Problem constants (fixed by the dataset)
#define CLASSES   128
#define M_IN      64      // inner dim (K)
#define N_OUT     32      // outputs per class
#define SPLIT     4       // blocks per class in main kernel
#define MAIN_THREADS  256 // 8 warps
#define HIST_THREADS  1024
#define MAX_HIST_BLOCKS 256

// ---------------- scratch (no allocations allowed) ----------------
__device__ int g_offsets[CLASSES + 1];
__device__ int g_cursor[CLASSES];
__device__ int g_perm[1 << 20];           // supports up to 1M samples
__device__ int g_blockcounts[MAX_HIST_BLOCKS * CLASSES];

// Detect whether the index buffer is int64 or int32.
// If int64 with small values, every odd int32 word (little-endian high half)
// is zero. One warp probes 32 odd words; writes result to *flag (shared).
__device__ __forceinline__ void detect_is64(const int* w, int nwords, int tid,
                                            int* flag) {
    if (tid < 32) {
        int idx = 2 * tid + 1;
        int v = (idx < nwords) ? w[idx] : 0;
        unsigned nz = __ballot_sync(0xFFFFFFFFu, v != 0);
        if (tid == 0) *flag = (nz == 0u) ? 1 : 0;
    }
}

__device__ __forceinline__ int load_class(const void* inds, int n, int is64) {
    int c;
    if (is64) c = (int)((const long long*)inds)[n];
    else      c = ((const int*)inds)[n];
    return c & (CLASSES - 1);   // defensive clamp
}

// ---------------- kernel 1: per-block histogram ----------------
__global__ void hist_kernel(const void* __restrict__ inds, int N) {
    __shared__ int s_cnt[CLASSES];
    __shared__ int s_is64;
    int t = threadIdx.x;
    if (t < CLASSES) s_cnt[t] = 0;
    detect_is64((const int*)inds, N, t, &s_is64);
    __syncthreads();
    int n = blockIdx.x * HIST_THREADS + t;
    if (n < N) atomicAdd(&s_cnt[load_class(inds, n, s_is64)], 1);
    __syncthreads();
    if (t < CLASSES) g_blockcounts[blockIdx.x * CLASSES + t] = s_cnt[t];
}

// ---------------- kernel 2: reduce + exclusive scan ----------------
__global__ void scan_kernel(int nblocks) {
    __shared__ int s[CLASSES];
    int t = threadIdx.x;   // 128 threads
    int sum = 0;
    for (int b = 0; b < nblocks; b++)
        sum += g_blockcounts[b * CLASSES + t];
    s[t] = sum;
    __syncthreads();
    // Hillis-Steele inclusive scan
    #pragma unroll
    for (int off = 1; off < CLASSES; off <<= 1) {
        int v = (t >= off) ? s[t - off] : 0;
        __syncthreads();
        s[t] += v;
        __syncthreads();
    }
    int incl = s[t];
    g_offsets[t + 1] = incl;
    if (t == 0) g_offsets[0] = 0;
    g_cursor[t] = incl - sum;   // exclusive prefix
}

// ---------------- kernel 3: scatter (two-level) ----------------
__global__ void scatter_kernel(const void* __restrict__ inds, int N) {
    __shared__ int s_cnt[CLASSES];
    __shared__ int s_base[CLASSES];
    __shared__ int s_is64;
    int t = threadIdx.x;
    if (t < CLASSES) s_cnt[t] = 0;
    detect_is64((const int*)inds, N, t, &s_is64);
    __syncthreads();
    int n = blockIdx.x * HIST_THREADS + t;
    int c = 0, loc = 0;
    if (n < N) {
        c = load_class(inds, n, s_is64);
        loc = atomicAdd(&s_cnt[c], 1);
    }
    __syncthreads();
    if (t < CLASSES) s_base[t] = atomicAdd(&g_cursor[t], s_cnt[t]);
    __syncthreads();
    if (n < N) g_perm[s_base[c] + loc] = n;
}

// ---------------- kernel 4: main gathered GEMV ----------------
// grid = CLASSES * SPLIT blocks, 256 threads (8 warps).
// Block owns class c = bid/SPLIT, quarter q = bid%SPLIT.
// W slice (32x64) + bias staged in shared. Warp processes 8 samples/iter:
// lane j accumulates output j for all 8 samples (register blocking on samples).
__global__ void __launch_bounds__(MAIN_THREADS, 4)
main_kernel(const float* __restrict__ x,
            const float* __restrict__ W,
            const float* __restrict__ b,
            float* __restrict__ out) {
    __shared__ float W_sh[N_OUT * 68];      // padded rows: stride 68 floats
    __shared__ float b_sh[N_OUT];
    __shared__ float x_sh[8][8][M_IN];      // [warp][sample][k]
    __shared__ int   n_idx[8][8];

    const int tid  = threadIdx.x;
    const int w    = tid >> 5;
    const int lane = tid & 31;

    const int c = blockIdx.x / SPLIT;
    const int q = blockIdx.x % SPLIT;

    // stage W slice (2048 floats) as float4, padded rows
    const float4* Wg = reinterpret_cast<const float4*>(W + (size_t)c * (N_OUT * M_IN));
    #pragma unroll
    for (int i = 0; i < 2; i++) {
        int idx = tid + i * MAIN_THREADS;           // 0..511 float4s
        float4 v = Wg[idx];
        int j = idx >> 4;                           // row (16 float4 per row)
        int kp = idx & 15;
        *reinterpret_cast<float4*>(&W_sh[j * 68 + kp * 4]) = v;
    }
    if (tid < N_OUT) b_sh[tid] = b[c * N_OUT + tid];

    const int start = g_offsets[c];
    const int total = g_offsets[c + 1] - start;
    const int chunk = (total + SPLIT - 1) / SPLIT;
    const int s0 = start + q * chunk;
    const int s1 = min(start + total, s0 + chunk);
    __syncthreads();

    for (int base = s0 + w * 8; base < s1; base += 8 * 8) {
        int rem = s1 - base; if (rem > 8) rem = 8;

        if (lane < 8) {
            int l = lane < rem ? lane : rem - 1;    // clamp (duplicates; stores skipped)
            n_idx[w][lane] = g_perm[base + l];
        }
        __syncwarp();

        // cooperative x load: 8 rows x 16 float4 = 128 float4s
        #pragma unroll
        for (int t = lane, i = 0; i < 4; i++, t += 32) {
            int row = t >> 4;
            int kp  = t & 15;
            int n   = n_idx[w][row];
            float4 v = *reinterpret_cast<const float4*>(x + (size_t)n * M_IN + kp * 4);
            *reinterpret_cast<float4*>(&x_sh[w][row][kp * 4]) = v;
        }
        __syncwarp();

        float acc0 = 0.f, acc1 = 0.f, acc2 = 0.f, acc3 = 0.f;
        float acc4 = 0.f, acc5 = 0.f, acc6 = 0.f, acc7 = 0.f;
        const float* wrow = &W_sh[lane * 68];
        #pragma unroll
        for (int k4 = 0; k4 < 16; k4++) {
            float4 wv = *reinterpret_cast<const float4*>(wrow + k4 * 4);
            #pragma unroll
            for (int s = 0; s < 8; s++) {
                float4 xv = *reinterpret_cast<const float4*>(&x_sh[w][s][k4 * 4]);
                float a = (s==0)?acc0:(s==1)?acc1:(s==2)?acc2:(s==3)?acc3:
                          (s==4)?acc4:(s==5)?acc5:(s==6)?acc6:acc7;
                a = fmaf(wv.x, xv.x, a);
                a = fmaf(wv.y, xv.y, a);
                a = fmaf(wv.z, xv.z, a);
                a = fmaf(wv.w, xv.w, a);
                if (s==0) acc0=a; else if (s==1) acc1=a; else if (s==2) acc2=a;
                else if (s==3) acc3=a; else if (s==4) acc4=a; else if (s==5) acc5=a;
                else if (s==6) acc6=a; else acc7=a;
            }
        }

        float bias = b_sh[lane];
        float accs[8] = {acc0,acc1,acc2,acc3,acc4,acc5,acc6,acc7};
        #pragma unroll
        for (int s = 0; s < 8; s++) {
            if (s < rem) {
                int n = n_idx[w][s];
                out[(size_t)n * N_OUT + lane] = accs[s] + bias;
            }
        }
        __syncwarp();
    }
}

// ---------------- launch ----------------
extern "C" void kernel_launch(void* const* d_in, const int* in_sizes, int n_in,
                              void* d_out, int out_size) {
    const float* x    = (const float*)d_in[0];
    const void*  inds = d_in[1];
    const float* W    = (const float*)d_in[2];
    const float* b    = (const float*)d_in[3];
    float*       out  = (float*)d_out;
    const int N = in_sizes[1];

    int hist_blocks = (N + HIST_THREADS - 1) / HIST_THREADS;
    if (hist_blocks > MAX_HIST_BLOCKS) hist_blocks = MAX_HIST_BLOCKS; // N<=1M per g_perm
    hist_kernel<<<hist_blocks, HIST_THREADS>>>(inds, N);
    scan_kernel<<<1, CLASSES>>>(hist_blocks);
    scatter_kernel<<<hist_blocks, HIST_THREADS>>>(inds, N);
    main_kernel<<<CLASSES * SPLIT, MAIN_THREADS>>>(x, W, b, out);
}